// round 16
// baseline (speedup 1.0000x reference)
#include <cuda_runtime.h>
#include <math.h>

#define Bz 16
#define Cc 64
#define Hh 128
#define Ww 128
#define HWp (Hh*Ww)
#define EPSV 2.220446049250313e-16f
#define NBAND 16
#define RCG 4            // router channel groups
#define RCH 16

// ---- device scratch ----
__device__ float g_part[Bz * NBAND * RCG * 8];
__device__ int   g_sel[Bz * 2];
__device__ float g_w1[Bz];

typedef unsigned long long u64;

__device__ __forceinline__ u64 pk(float lo, float hi) {
    u64 r; asm("mov.b64 %0, {%1,%2};" : "=l"(r) : "f"(lo), "f"(hi)); return r;
}
__device__ __forceinline__ void upk(u64 v, float& lo, float& hi) {
    asm("mov.b64 {%0,%1}, %2;" : "=f"(lo), "=f"(hi) : "l"(v));
}
__device__ __forceinline__ void fma2(u64& d, u64 a, u64 b) {
    asm("fma.rn.f32x2 %0, %1, %2, %0;" : "+l"(d) : "l"(a), "l"(b));
}

// ============================================================
// Router v4: cp.async triple-buffered channel tiles + vectorized
// u64-pair weight broadcasts. grid (Bz, NBAND, RCG), block 256.
// Tile col = gw + 4 (16B-aligned cp.async chunks, zfill halo).
// ============================================================
#define RT_ROWS 14
#define RT_COLS 136
#define RT_ELEM (RT_ROWS * RT_COLS)    // 1904
#define RT_CHUNK (RT_ROWS * 34)        // 476 16B chunks

__global__ __launch_bounds__(256) void router_kernel(
    const float* __restrict__ x,   // [B,C,H,W]
    const float* __restrict__ rw,  // [1,C,7,7]
    const float* __restrict__ rb,  // [1]
    const float* __restrict__ wg)  // [HW, E]
{
    __shared__ __align__(16) float sT[3][RT_ELEM];        // 22848 B
    __shared__ __align__(16) u64   sW2[RCH * 7 * 8];      // [c][dh][8] pairs, 7168 B
    __shared__ float sPart[8][8];

    int b    = blockIdx.x;
    int band = blockIdx.y;
    int cg   = blockIdx.z;
    int h0   = band * 8;
    int t    = threadIdx.x;
    int row  = t >> 5;      // 0..7
    int wq   = t & 31;
    int ws   = wq * 4;

    // weights as duplicated pairs, padded rows of 8
    for (int i = t; i < RCH * 49; i += 256) {
        int c  = i / 49;
        int k  = i - c * 49;
        int dh = k / 7;
        int dw = k - dh * 7;
        float w = rw[cg * RCH * 49 + i];
        sW2[(c * 7 + dh) * 8 + dw] = pk(w, w);
    }

    const float* xb = x + ((long long)b * Cc + cg * RCH) * HWp;
    unsigned int sbase = (unsigned int)__cvta_generic_to_shared(&sT[0][0]);

    // issue channel-tile ch into buffer buf
    auto issue = [&](int ch, int buf) {
        const float* xc = xb + (long long)ch * HWp;
        for (int k = t; k < RT_CHUNK; k += 256) {
            int rr  = k / 34;
            int c16 = k - rr * 34;
            int gh  = h0 - 3 + rr;
            bool ok = (gh >= 0) & (gh < Hh) & (c16 >= 1) & (c16 <= 32);
            const float* src = ok ? (xc + gh * Ww + (c16 * 4 - 4)) : xb;
            int sz = ok ? 16 : 0;
            unsigned int dst = sbase + (unsigned int)((buf * RT_ELEM + rr * RT_COLS + c16 * 4) * 4);
            asm volatile("cp.async.cg.shared.global [%0], [%1], 16, %2;"
                         :: "r"(dst), "l"(src), "r"(sz) : "memory");
        }
        asm volatile("cp.async.commit_group;" ::: "memory");
    };

    issue(0, 0);

    u64 acc01 = pk(0.f, 0.f);
    u64 acc23 = pk(0.f, 0.f);

    for (int c = 0; c < RCH; ++c) {
        if (c + 1 < RCH) {
            issue(c + 1, (c + 1) % 3);
            asm volatile("cp.async.wait_group 1;" ::: "memory");
        } else {
            asm volatile("cp.async.wait_group 0;" ::: "memory");
        }
        __syncthreads();

        const float* tb = sT[c % 3];
        const u64*   wc = sW2 + c * 7 * 8;
        #pragma unroll
        for (int dh = 0; dh < 7; ++dh) {
            const float* rp = tb + (row + dh) * RT_COLS + ws;
            float4 v0 = *reinterpret_cast<const float4*>(rp);
            float4 v1 = *reinterpret_cast<const float4*>(rp + 4);
            float4 v2 = *reinterpret_cast<const float4*>(rp + 8);
            float tt[12];
            tt[0]=v0.x; tt[1]=v0.y; tt[2]=v0.z;  tt[3]=v0.w;
            tt[4]=v1.x; tt[5]=v1.y; tt[6]=v1.z;  tt[7]=v1.w;
            tt[8]=v2.x; tt[9]=v2.y; tt[10]=v2.z; tt[11]=v2.w;
            u64 p[9];
            #pragma unroll
            for (int j = 0; j < 9; ++j) p[j] = pk(tt[j + 1], tt[j + 2]);
            const ulonglong2* wr = reinterpret_cast<const ulonglong2*>(wc + dh * 8);
            ulonglong2 w01 = wr[0], w23 = wr[1], w45 = wr[2], w67 = wr[3];
            u64 wv[7] = { w01.x, w01.y, w23.x, w23.y, w45.x, w45.y, w67.x };
            #pragma unroll
            for (int dw = 0; dw < 7; ++dw) {
                fma2(acc01, p[dw],     wv[dw]);
                fma2(acc23, p[dw + 2], wv[dw]);
            }
        }
    }

    float rbv = (cg == 0) ? rb[0] : 0.f;
    float rv[4];
    upk(acc01, rv[0], rv[1]);
    upk(acc23, rv[2], rv[3]);
    #pragma unroll
    for (int px = 0; px < 4; ++px) rv[px] += rbv;

    float lacc[8];
    #pragma unroll
    for (int e = 0; e < 8; ++e) lacc[e] = 0.f;
    int h = h0 + row;
    #pragma unroll
    for (int px = 0; px < 4; ++px) {
        int p = h * Ww + ws + px;
        const float4* wp = reinterpret_cast<const float4*>(wg + (long long)p * 8);
        float4 a  = wp[0];
        float4 bb = wp[1];
        float r = rv[px];
        lacc[0] += r * a.x;  lacc[1] += r * a.y;  lacc[2] += r * a.z;  lacc[3] += r * a.w;
        lacc[4] += r * bb.x; lacc[5] += r * bb.y; lacc[6] += r * bb.z; lacc[7] += r * bb.w;
    }

    int lane = t & 31, warp = t >> 5;
    #pragma unroll
    for (int e = 0; e < 8; ++e) {
        float v = lacc[e];
        #pragma unroll
        for (int off = 16; off; off >>= 1) v += __shfl_down_sync(0xffffffffu, v, off);
        if (lane == 0) sPart[warp][e] = v;
    }
    __syncthreads();
    if (t < 8) {
        float s = 0.f;
        #pragma unroll
        for (int w2 = 0; w2 < 8; ++w2) s += sPart[w2][t];
        g_part[(((b * NBAND) + band) * RCG + cg) * 8 + t] = s;
    }
}

// ============================================================
// Gating: logits -> top-2 -> gates, deterministic loss.
// ============================================================
__global__ void gate_kernel(float* __restrict__ out, long long loss_idx)
{
    __shared__ float sg0[Bz], sg1[Bz];
    __shared__ int   si0[Bz], si1[Bz];
    int t = threadIdx.x;

    if (t < Bz) {
        float l[8];
        #pragma unroll
        for (int e = 0; e < 8; ++e) {
            float s = 0.f;
            for (int k = 0; k < NBAND * RCG; ++k)
                s += g_part[(t * NBAND * RCG + k) * 8 + e];
            l[e] = s;
        }
        int i0 = 0; float m0 = l[0];
        #pragma unroll
        for (int e = 1; e < 8; ++e) if (l[e] > m0) { m0 = l[e]; i0 = e; }
        int i1 = (i0 == 0) ? 1 : 0; float m1 = l[i1];
        #pragma unroll
        for (int e = 0; e < 8; ++e)
            if (e != i0 && l[e] > m1) { m1 = l[e]; i1 = e; }
        float ex = expf(m1 - m0);
        float g0 = 1.f / (1.f + ex);
        float g1 = ex / (1.f + ex);
        g_sel[t * 2]     = i0;
        g_sel[t * 2 + 1] = i1;
        g_w1[t] = (g1 > 0.f) ? 1.f : 0.f;
        si0[t] = i0; si1[t] = i1; sg0[t] = g0; sg1[t] = g1;
    }
    __syncthreads();
    if (t == 0) {
        float imp[8]; float ldc[8];
        #pragma unroll
        for (int e = 0; e < 8; ++e) { imp[e] = 0.f; ldc[e] = 0.f; }
        for (int bb = 0; bb < Bz; ++bb) {
            imp[si0[bb]] += sg0[bb];
            imp[si1[bb]] += sg1[bb];
            ldc[si0[bb]] += 1.f;
            if (sg1[bb] > 0.f) ldc[si1[bb]] += 1.f;
        }
        float mi = 0.f, ml = 0.f;
        for (int e = 0; e < 8; ++e) { mi += imp[e]; ml += ldc[e]; }
        mi *= 0.125f; ml *= 0.125f;
        float vi = 0.f, vl = 0.f;
        for (int e = 0; e < 8; ++e) {
            float d  = imp[e] - mi; vi += d * d;
            float dl = ldc[e] - ml; vl += dl * dl;
        }
        vi *= (1.f / 7.f); vl *= (1.f / 7.f);
        float loss = (vi / (mi * mi + 1e-10f) + vl / (ml * ml + 1e-10f)) * 0.01f;
        out[loss_idx] = loss;
    }
}

// ============================================================
// Main fused kernel v9: v8 (cp.async tile, LSE epilogue) + vectorized
// u64-pair weight broadcasts ([f][cl][dh][8] padded, ulonglong2 reads).
// 4 ch/block, 4-row strips, 8 warps: warp = (row, ch-pair), 3 blocks/SM.
// ============================================================
#define MC4 4
#define MROW 10
#define MCOL 136                   // col = gw + 4; 34 x 16B chunks per row
#define MTILE (MC4 * MROW * MCOL)  // 5440 words
#define NCHUNK (MC4 * MROW * 34)   // 1360 16B chunks

__device__ __forceinline__ float lse_combine(float u, float v, float w1,
                                             float add) {
    float M = fmaxf(u, v);
    float lse = M + __logf(1.0f + __expf(-fabsf(u - v)));
    return ((w1 > 0.f) ? lse : u) + add;
}

__global__ __launch_bounds__(256, 3) void main_kernel(
    const float* __restrict__ x,    // [B,C,H,W]
    const float* __restrict__ ew,   // [E,C,1,7,7]
    const float* __restrict__ eb,   // [E,C]
    const float* __restrict__ sw,   // [C,1,7,7]
    const float* __restrict__ sb,   // [C]
    float* __restrict__ out)        // [B,HW,C]
{
    __shared__ __align__(16) float sIn[MTILE];             // 21760 B
    __shared__ __align__(16) u64   sWd[3 * MC4 * 7 * 8];   // [f][cl][dh][8], 5376 B
    __shared__ __align__(16) float sOut[MC4 * 4 * 128];    // 8192 B

    int hb = blockIdx.x;
    int cg = blockIdx.y;
    int b  = blockIdx.z;
    int h0 = hb * 4;
    int t  = threadIdx.x;
    int w  = t >> 5;
    int qx = t & 31;
    int r  = w & 3;
    int cp = w >> 2;

    int e0  = g_sel[b * 2];
    int e1i = g_sel[b * 2 + 1];
    float w1 = g_w1[b];

    const float* xb = x + ((long long)b * Cc + cg * MC4) * HWp;

    // ---- tile load via cp.async.cg (16B chunks, zfill halo) ----
    {
        unsigned int sbase = (unsigned int)__cvta_generic_to_shared(sIn);
        for (int k = t; k < NCHUNK; k += 256) {
            int c   = k / 340;
            int rem = k - c * 340;
            int rr  = rem / 34;
            int c16 = rem - rr * 34;
            int gh  = h0 - 3 + rr;
            bool ok = (gh >= 0) & (gh < Hh) & (c16 >= 1) & (c16 <= 32);
            const float* src = ok ? (xb + c * HWp + gh * Ww + (c16 * 4 - 4)) : xb;
            int sz = ok ? 16 : 0;
            unsigned int dst = sbase + (unsigned int)((c * (MROW * MCOL) + rr * MCOL + c16 * 4) * 4);
            asm volatile("cp.async.cg.shared.global [%0], [%1], 16, %2;"
                         :: "r"(dst), "l"(src), "r"(sz) : "memory");
        }
        asm volatile("cp.async.commit_group;" ::: "memory");
    }
    // ---- weights as duplicated pairs, padded [f][cl][dh][8] ----
    for (int idx = t; idx < 3 * MC4 * 49; idx += 256) {
        int f   = idx / (MC4 * 49);
        int rem = idx - f * (MC4 * 49);
        int cl  = rem / 49;
        int k   = rem - cl * 49;
        int dh  = k / 7;
        int dw  = k - dh * 7;
        int gc  = cg * MC4 + cl;
        float wv = (f == 0) ? sw[gc * 49 + k]
                 : (f == 1) ? ew[e0  * (Cc * 49) + gc * 49 + k]
                            : ew[e1i * (Cc * 49) + gc * 49 + k];
        sWd[((f * MC4 + cl) * 7 + dh) * 8 + dw] = pk(wv, wv);
    }
    asm volatile("cp.async.wait_group 0;" ::: "memory");
    __syncthreads();

    // ---- compute: loop 2 channels of this warp's pair ----
    #pragma unroll
    for (int ci = 0; ci < 2; ++ci) {
        int cl = cp * 2 + ci;
        const float* inc = sIn + cl * (MROW * MCOL) + qx * 4;

        u64 acc[3][2];
        u64 z = pk(0.f, 0.f);
        #pragma unroll
        for (int f = 0; f < 3; ++f) { acc[f][0] = z; acc[f][1] = z; }

        #pragma unroll
        for (int dh = 0; dh < 7; ++dh) {
            const float* rp = inc + (r + dh) * MCOL;
            float4 v0 = *reinterpret_cast<const float4*>(rp);
            float4 v1 = *reinterpret_cast<const float4*>(rp + 4);
            float4 v2 = *reinterpret_cast<const float4*>(rp + 8);
            float tt[12];
            tt[0]=v0.x; tt[1]=v0.y; tt[2]=v0.z;  tt[3]=v0.w;
            tt[4]=v1.x; tt[5]=v1.y; tt[6]=v1.z;  tt[7]=v1.w;
            tt[8]=v2.x; tt[9]=v2.y; tt[10]=v2.z; tt[11]=v2.w;
            u64 p[9];
            #pragma unroll
            for (int j = 0; j < 9; ++j) p[j] = pk(tt[j + 1], tt[j + 2]);
            #pragma unroll
            for (int f = 0; f < 3; ++f) {
                const ulonglong2* wr = reinterpret_cast<const ulonglong2*>(
                    sWd + ((f * MC4 + cl) * 7 + dh) * 8);
                ulonglong2 w01 = wr[0], w23 = wr[1], w45 = wr[2], w67 = wr[3];
                u64 wv[7] = { w01.x, w01.y, w23.x, w23.y, w45.x, w45.y, w67.x };
                #pragma unroll
                for (int dw = 0; dw < 7; ++dw) {
                    fma2(acc[f][0], p[dw],     wv[dw]);  // px 0,1
                    fma2(acc[f][1], p[dw + 2], wv[dw]);  // px 2,3
                }
            }
        }

        // ---- LSE epilogue, stage to smem ----
        int gc = cg * MC4 + cl;
        float bS = sb[gc];
        float b0 = eb[e0  * Cc + gc];
        float b1 = eb[e1i * Cc + gc];

        float aS0,aS1,aS2,aS3, a00,a01,a02,a03, a10,a11,a12,a13;
        upk(acc[0][0], aS0, aS1); upk(acc[0][1], aS2, aS3);
        upk(acc[1][0], a00, a01); upk(acc[1][1], a02, a03);
        upk(acc[2][0], a10, a11); upk(acc[2][1], a12, a13);

        float4 res;
        res.x = lse_combine(a00 + b0, a10 + b1, w1, aS0 + bS);
        res.y = lse_combine(a01 + b0, a11 + b1, w1, aS1 + bS);
        res.z = lse_combine(a02 + b0, a12 + b1, w1, aS2 + bS);
        res.w = lse_combine(a03 + b0, a13 + b1, w1, aS3 + bS);
        *reinterpret_cast<float4*>(sOut + (cl * 4 + r) * 128 + qx * 4) = res;
    }
    __syncthreads();

    // ---- c-fastest store: STG.128 of 4 channels per px ----
    long long obase = ((long long)b * HWp + h0 * Ww) * Cc + cg * MC4;
    #pragma unroll
    for (int k = 0; k < 2; ++k) {
        int e   = t + k * 256;
        int row = e >> 7;
        int px  = e & 127;
        float4 v;
        v.x = sOut[(0 * 4 + row) * 128 + px];
        v.y = sOut[(1 * 4 + row) * 128 + px];
        v.z = sOut[(2 * 4 + row) * 128 + px];
        v.w = sOut[(3 * 4 + row) * 128 + px];
        *reinterpret_cast<float4*>(out + obase + (long long)(row * Ww + px) * Cc) = v;
    }
}

// ============================================================
extern "C" void kernel_launch(void* const* d_in, const int* in_sizes, int n_in,
                              void* d_out, int out_size) {
    const float* x  = (const float*)d_in[0];
    const float* rw = (const float*)d_in[1];
    const float* rb = (const float*)d_in[2];
    const float* wg = (const float*)d_in[3];
    const float* ew = (const float*)d_in[4];
    const float* eb = (const float*)d_in[5];
    const float* sw = (const float*)d_in[6];
    const float* sb = (const float*)d_in[7];
    float* out = (float*)d_out;

    router_kernel<<<dim3(Bz, NBAND, RCG), 256>>>(x, rw, rb, wg);
    gate_kernel<<<1, 32>>>(out, (long long)out_size - 1);
    main_kernel<<<dim3(Hh / 4, Cc / MC4, Bz), 256>>>(x, ew, eb, sw, sb, out);
}

// round 17
// speedup vs baseline: 1.1337x; 1.1337x over previous
#include <cuda_runtime.h>
#include <math.h>

#define Bz 16
#define Cc 64
#define Hh 128
#define Ww 128
#define HWp (Hh*Ww)
#define EPSV 2.220446049250313e-16f
#define NBAND 16
#define RCG 4            // router channel groups
#define RCH 16

// ---- device scratch ----
__device__ float g_part[Bz * NBAND * RCG * 8];
__device__ int   g_sel[Bz * 2];
__device__ float g_w1[Bz];

typedef unsigned long long u64;

__device__ __forceinline__ u64 pk(float lo, float hi) {
    u64 r; asm("mov.b64 %0, {%1,%2};" : "=l"(r) : "f"(lo), "f"(hi)); return r;
}
__device__ __forceinline__ void upk(u64 v, float& lo, float& hi) {
    asm("mov.b64 {%0,%1}, %2;" : "=f"(lo), "=f"(hi) : "l"(v));
}
__device__ __forceinline__ void fma2(u64& d, u64 a, u64 b) {
    asm("fma.rn.f32x2 %0, %1, %2, %0;" : "+l"(d) : "l"(a), "l"(b));
}

// ============================================================
// Router v4 (R16, 82.2us): cp.async triple-buffered channel tiles +
// vectorized u64-pair weight broadcasts. grid (Bz, NBAND, RCG), block 256.
// ============================================================
#define RT_ROWS 14
#define RT_COLS 136
#define RT_ELEM (RT_ROWS * RT_COLS)    // 1904
#define RT_CHUNK (RT_ROWS * 34)        // 476 16B chunks

__global__ __launch_bounds__(256) void router_kernel(
    const float* __restrict__ x,   // [B,C,H,W]
    const float* __restrict__ rw,  // [1,C,7,7]
    const float* __restrict__ rb,  // [1]
    const float* __restrict__ wg)  // [HW, E]
{
    __shared__ __align__(16) float sT[3][RT_ELEM];
    __shared__ __align__(16) u64   sW2[RCH * 7 * 8];
    __shared__ float sPart[8][8];

    int b    = blockIdx.x;
    int band = blockIdx.y;
    int cg   = blockIdx.z;
    int h0   = band * 8;
    int t    = threadIdx.x;
    int row  = t >> 5;
    int wq   = t & 31;
    int ws   = wq * 4;

    for (int i = t; i < RCH * 49; i += 256) {
        int c  = i / 49;
        int k  = i - c * 49;
        int dh = k / 7;
        int dw = k - dh * 7;
        float w = rw[cg * RCH * 49 + i];
        sW2[(c * 7 + dh) * 8 + dw] = pk(w, w);
    }

    const float* xb = x + ((long long)b * Cc + cg * RCH) * HWp;
    unsigned int sbase = (unsigned int)__cvta_generic_to_shared(&sT[0][0]);

    auto issue = [&](int ch, int buf) {
        const float* xc = xb + (long long)ch * HWp;
        for (int k = t; k < RT_CHUNK; k += 256) {
            int rr  = k / 34;
            int c16 = k - rr * 34;
            int gh  = h0 - 3 + rr;
            bool ok = (gh >= 0) & (gh < Hh) & (c16 >= 1) & (c16 <= 32);
            const float* src = ok ? (xc + gh * Ww + (c16 * 4 - 4)) : xb;
            int sz = ok ? 16 : 0;
            unsigned int dst = sbase + (unsigned int)((buf * RT_ELEM + rr * RT_COLS + c16 * 4) * 4);
            asm volatile("cp.async.cg.shared.global [%0], [%1], 16, %2;"
                         :: "r"(dst), "l"(src), "r"(sz) : "memory");
        }
        asm volatile("cp.async.commit_group;" ::: "memory");
    };

    issue(0, 0);

    u64 acc01 = pk(0.f, 0.f);
    u64 acc23 = pk(0.f, 0.f);

    for (int c = 0; c < RCH; ++c) {
        if (c + 1 < RCH) {
            issue(c + 1, (c + 1) % 3);
            asm volatile("cp.async.wait_group 1;" ::: "memory");
        } else {
            asm volatile("cp.async.wait_group 0;" ::: "memory");
        }
        __syncthreads();

        const float* tb = sT[c % 3];
        const u64*   wc = sW2 + c * 7 * 8;
        #pragma unroll
        for (int dh = 0; dh < 7; ++dh) {
            const float* rp = tb + (row + dh) * RT_COLS + ws;
            float4 v0 = *reinterpret_cast<const float4*>(rp);
            float4 v1 = *reinterpret_cast<const float4*>(rp + 4);
            float4 v2 = *reinterpret_cast<const float4*>(rp + 8);
            float tt[12];
            tt[0]=v0.x; tt[1]=v0.y; tt[2]=v0.z;  tt[3]=v0.w;
            tt[4]=v1.x; tt[5]=v1.y; tt[6]=v1.z;  tt[7]=v1.w;
            tt[8]=v2.x; tt[9]=v2.y; tt[10]=v2.z; tt[11]=v2.w;
            u64 p[9];
            #pragma unroll
            for (int j = 0; j < 9; ++j) p[j] = pk(tt[j + 1], tt[j + 2]);
            const ulonglong2* wr = reinterpret_cast<const ulonglong2*>(wc + dh * 8);
            ulonglong2 w01 = wr[0], w23 = wr[1], w45 = wr[2], w67 = wr[3];
            u64 wv[7] = { w01.x, w01.y, w23.x, w23.y, w45.x, w45.y, w67.x };
            #pragma unroll
            for (int dw = 0; dw < 7; ++dw) {
                fma2(acc01, p[dw],     wv[dw]);
                fma2(acc23, p[dw + 2], wv[dw]);
            }
        }
    }

    float rbv = (cg == 0) ? rb[0] : 0.f;
    float rv[4];
    upk(acc01, rv[0], rv[1]);
    upk(acc23, rv[2], rv[3]);
    #pragma unroll
    for (int px = 0; px < 4; ++px) rv[px] += rbv;

    float lacc[8];
    #pragma unroll
    for (int e = 0; e < 8; ++e) lacc[e] = 0.f;
    int h = h0 + row;
    #pragma unroll
    for (int px = 0; px < 4; ++px) {
        int p = h * Ww + ws + px;
        const float4* wp = reinterpret_cast<const float4*>(wg + (long long)p * 8);
        float4 a  = wp[0];
        float4 bb = wp[1];
        float r = rv[px];
        lacc[0] += r * a.x;  lacc[1] += r * a.y;  lacc[2] += r * a.z;  lacc[3] += r * a.w;
        lacc[4] += r * bb.x; lacc[5] += r * bb.y; lacc[6] += r * bb.z; lacc[7] += r * bb.w;
    }

    int lane = t & 31, warp = t >> 5;
    #pragma unroll
    for (int e = 0; e < 8; ++e) {
        float v = lacc[e];
        #pragma unroll
        for (int off = 16; off; off >>= 1) v += __shfl_down_sync(0xffffffffu, v, off);
        if (lane == 0) sPart[warp][e] = v;
    }
    __syncthreads();
    if (t < 8) {
        float s = 0.f;
        #pragma unroll
        for (int w2 = 0; w2 < 8; ++w2) s += sPart[w2][t];
        g_part[(((b * NBAND) + band) * RCG + cg) * 8 + t] = s;
    }
}

// ============================================================
// Gating: logits -> top-2 -> gates, deterministic loss.
// ============================================================
__global__ void gate_kernel(float* __restrict__ out, long long loss_idx)
{
    __shared__ float sg0[Bz], sg1[Bz];
    __shared__ int   si0[Bz], si1[Bz];
    int t = threadIdx.x;

    if (t < Bz) {
        float l[8];
        #pragma unroll
        for (int e = 0; e < 8; ++e) {
            float s = 0.f;
            for (int k = 0; k < NBAND * RCG; ++k)
                s += g_part[(t * NBAND * RCG + k) * 8 + e];
            l[e] = s;
        }
        int i0 = 0; float m0 = l[0];
        #pragma unroll
        for (int e = 1; e < 8; ++e) if (l[e] > m0) { m0 = l[e]; i0 = e; }
        int i1 = (i0 == 0) ? 1 : 0; float m1 = l[i1];
        #pragma unroll
        for (int e = 0; e < 8; ++e)
            if (e != i0 && l[e] > m1) { m1 = l[e]; i1 = e; }
        float ex = expf(m1 - m0);
        float g0 = 1.f / (1.f + ex);
        float g1 = ex / (1.f + ex);
        g_sel[t * 2]     = i0;
        g_sel[t * 2 + 1] = i1;
        g_w1[t] = (g1 > 0.f) ? 1.f : 0.f;
        si0[t] = i0; si1[t] = i1; sg0[t] = g0; sg1[t] = g1;
    }
    __syncthreads();
    if (t == 0) {
        float imp[8]; float ldc[8];
        #pragma unroll
        for (int e = 0; e < 8; ++e) { imp[e] = 0.f; ldc[e] = 0.f; }
        for (int bb = 0; bb < Bz; ++bb) {
            imp[si0[bb]] += sg0[bb];
            imp[si1[bb]] += sg1[bb];
            ldc[si0[bb]] += 1.f;
            if (sg1[bb] > 0.f) ldc[si1[bb]] += 1.f;
        }
        float mi = 0.f, ml = 0.f;
        for (int e = 0; e < 8; ++e) { mi += imp[e]; ml += ldc[e]; }
        mi *= 0.125f; ml *= 0.125f;
        float vi = 0.f, vl = 0.f;
        for (int e = 0; e < 8; ++e) {
            float d  = imp[e] - mi; vi += d * d;
            float dl = ldc[e] - ml; vl += dl * dl;
        }
        vi *= (1.f / 7.f); vl *= (1.f / 7.f);
        float loss = (vi / (mi * mi + 1e-10f) + vl / (ml * ml + 1e-10f)) * 0.01f;
        out[loss_idx] = loss;
    }
}

// ============================================================
// Main fused kernel v10: occupancy-max scalar. Same tiling/grid as v9
// (4 ch/block, 4-row strips, cp.async tile, LSE epilogue, staged store)
// but scalar FFMA (low regs) + launch_bounds(256,5) => 40 warps/SM.
// ============================================================
#define MC4 4
#define MROW 10
#define MCOL 136                   // col = gw + 4
#define MTILE (MC4 * MROW * MCOL)  // 5440 words
#define NCHUNK (MC4 * MROW * 34)   // 1360 16B chunks

__device__ __forceinline__ float lse_combine(float u, float v, float w1,
                                             float add) {
    float M = fmaxf(u, v);
    float lse = M + __logf(1.0f + __expf(-fabsf(u - v)));
    return ((w1 > 0.f) ? lse : u) + add;
}

__global__ __launch_bounds__(256, 5) void main_kernel(
    const float* __restrict__ x,    // [B,C,H,W]
    const float* __restrict__ ew,   // [E,C,1,7,7]
    const float* __restrict__ eb,   // [E,C]
    const float* __restrict__ sw,   // [C,1,7,7]
    const float* __restrict__ sb,   // [C]
    float* __restrict__ out)        // [B,HW,C]
{
    __shared__ __align__(16) float sIn[MTILE];             // 21760 B
    __shared__ __align__(16) float sWs[3 * MC4 * 7 * 8];   // [f][cl][dh][8] f32, 2688 B
    __shared__ __align__(16) float sOut[MC4 * 4 * 128];    // 8192 B

    int hb = blockIdx.x;
    int cg = blockIdx.y;
    int b  = blockIdx.z;
    int h0 = hb * 4;
    int t  = threadIdx.x;
    int w  = t >> 5;
    int qx = t & 31;
    int r  = w & 3;
    int cp = w >> 2;

    int e0  = g_sel[b * 2];
    int e1i = g_sel[b * 2 + 1];
    float w1 = g_w1[b];

    const float* xb = x + ((long long)b * Cc + cg * MC4) * HWp;

    // ---- tile load via cp.async.cg (16B chunks, zfill halo) ----
    {
        unsigned int sbase = (unsigned int)__cvta_generic_to_shared(sIn);
        for (int k = t; k < NCHUNK; k += 256) {
            int c   = k / 340;
            int rem = k - c * 340;
            int rr  = rem / 34;
            int c16 = rem - rr * 34;
            int gh  = h0 - 3 + rr;
            bool ok = (gh >= 0) & (gh < Hh) & (c16 >= 1) & (c16 <= 32);
            const float* src = ok ? (xb + c * HWp + gh * Ww + (c16 * 4 - 4)) : xb;
            int sz = ok ? 16 : 0;
            unsigned int dst = sbase + (unsigned int)((c * (MROW * MCOL) + rr * MCOL + c16 * 4) * 4);
            asm volatile("cp.async.cg.shared.global [%0], [%1], 16, %2;"
                         :: "r"(dst), "l"(src), "r"(sz) : "memory");
        }
        asm volatile("cp.async.commit_group;" ::: "memory");
    }
    // ---- weights f32, padded [f][cl][dh][8] ----
    for (int idx = t; idx < 3 * MC4 * 49; idx += 256) {
        int f   = idx / (MC4 * 49);
        int rem = idx - f * (MC4 * 49);
        int cl  = rem / 49;
        int k   = rem - cl * 49;
        int dh  = k / 7;
        int dw  = k - dh * 7;
        int gc  = cg * MC4 + cl;
        float wv = (f == 0) ? sw[gc * 49 + k]
                 : (f == 1) ? ew[e0  * (Cc * 49) + gc * 49 + k]
                            : ew[e1i * (Cc * 49) + gc * 49 + k];
        sWs[((f * MC4 + cl) * 7 + dh) * 8 + dw] = wv;
    }
    asm volatile("cp.async.wait_group 0;" ::: "memory");
    __syncthreads();

    // ---- compute: loop 2 channels of this warp's pair, scalar FFMA ----
    #pragma unroll
    for (int ci = 0; ci < 2; ++ci) {
        int cl = cp * 2 + ci;
        const float* inc = sIn + cl * (MROW * MCOL) + qx * 4;

        float acc[3][4];
        #pragma unroll
        for (int f = 0; f < 3; ++f)
            #pragma unroll
            for (int j = 0; j < 4; ++j) acc[f][j] = 0.f;

        #pragma unroll
        for (int dh = 0; dh < 7; ++dh) {
            const float* rp = inc + (r + dh) * MCOL;
            float4 v0 = *reinterpret_cast<const float4*>(rp);
            float4 v1 = *reinterpret_cast<const float4*>(rp + 4);
            float4 v2 = *reinterpret_cast<const float4*>(rp + 8);
            float tt[12];
            tt[0]=v0.x; tt[1]=v0.y; tt[2]=v0.z;  tt[3]=v0.w;
            tt[4]=v1.x; tt[5]=v1.y; tt[6]=v1.z;  tt[7]=v1.w;
            tt[8]=v2.x; tt[9]=v2.y; tt[10]=v2.z; tt[11]=v2.w;
            #pragma unroll
            for (int f = 0; f < 3; ++f) {
                const float* wf = sWs + ((f * MC4 + cl) * 7 + dh) * 8;
                float4 wa = *reinterpret_cast<const float4*>(wf);      // broadcast
                float4 wb = *reinterpret_cast<const float4*>(wf + 4);  // broadcast
                float wv[7] = { wa.x, wa.y, wa.z, wa.w, wb.x, wb.y, wb.z };
                #pragma unroll
                for (int dw = 0; dw < 7; ++dw) {
                    float wx = wv[dw];
                    #pragma unroll
                    for (int j = 0; j < 4; ++j)
                        acc[f][j] += tt[j + 1 + dw] * wx;   // px j: col qx*4+j+1+dw
                }
            }
        }

        // ---- LSE epilogue, stage to smem ----
        int gc = cg * MC4 + cl;
        float bS = sb[gc];
        float b0 = eb[e0  * Cc + gc];
        float b1 = eb[e1i * Cc + gc];

        float4 res;
        res.x = lse_combine(acc[1][0] + b0, acc[2][0] + b1, w1, acc[0][0] + bS);
        res.y = lse_combine(acc[1][1] + b0, acc[2][1] + b1, w1, acc[0][1] + bS);
        res.z = lse_combine(acc[1][2] + b0, acc[2][2] + b1, w1, acc[0][2] + bS);
        res.w = lse_combine(acc[1][3] + b0, acc[2][3] + b1, w1, acc[0][3] + bS);
        *reinterpret_cast<float4*>(sOut + (cl * 4 + r) * 128 + qx * 4) = res;
    }
    __syncthreads();

    // ---- c-fastest store: STG.128 of 4 channels per px ----
    long long obase = ((long long)b * HWp + h0 * Ww) * Cc + cg * MC4;
    #pragma unroll
    for (int k = 0; k < 2; ++k) {
        int e   = t + k * 256;
        int row = e >> 7;
        int px  = e & 127;
        float4 v;
        v.x = sOut[(0 * 4 + row) * 128 + px];
        v.y = sOut[(1 * 4 + row) * 128 + px];
        v.z = sOut[(2 * 4 + row) * 128 + px];
        v.w = sOut[(3 * 4 + row) * 128 + px];
        *reinterpret_cast<float4*>(out + obase + (long long)(row * Ww + px) * Cc) = v;
    }
}

// ============================================================
extern "C" void kernel_launch(void* const* d_in, const int* in_sizes, int n_in,
                              void* d_out, int out_size) {
    const float* x  = (const float*)d_in[0];
    const float* rw = (const float*)d_in[1];
    const float* rb = (const float*)d_in[2];
    const float* wg = (const float*)d_in[3];
    const float* ew = (const float*)d_in[4];
    const float* eb = (const float*)d_in[5];
    const float* sw = (const float*)d_in[6];
    const float* sb = (const float*)d_in[7];
    float* out = (float*)d_out;

    router_kernel<<<dim3(Bz, NBAND, RCG), 256>>>(x, rw, rb, wg);
    gate_kernel<<<1, 32>>>(out, (long long)out_size - 1);
    main_kernel<<<dim3(Hh / 4, Cc / MC4, Bz), 256>>>(x, ew, eb, sw, sb, out);
}